// round 4
// baseline (speedup 1.0000x reference)
#include <cuda_runtime.h>
#include <cuda_bf16.h>
#include <float.h>
#include <math.h>

#define R_ROIS 1000
#define N_CLASS 81
#define N_FG 80
#define IMG_H 600.0f
#define IMG_W 800.0f
#define SCORE_THRESH 0.05f
#define NMS_THRESH 0.5f
#define CAP 1024     // legacy-path capacity (pow2 padded)
#define FAST 128     // fast-path capacity: 4 slots * 32 lanes

// Scratch (no cudaMalloc allowed): transposed probs [class][roi]
__device__ float g_probT[N_CLASS * R_ROIS];

// ---------------------------------------------------------------------------
// Kernel A: softmax over classes, one WARP per RoI. (unchanged from R2)
// ---------------------------------------------------------------------------
__global__ __launch_bounds__(256) void softmax_kernel(const float* __restrict__ roi_score) {
    const int warp = (blockIdx.x * blockDim.x + threadIdx.x) >> 5;
    const int lane = threadIdx.x & 31;
    if (warp >= R_ROIS) return;

    const float* sc = roi_score + warp * N_CLASS;
    int c0 = lane, c1 = lane + 32, c2 = lane + 64;
    float s0 = sc[c0];
    float s1 = (c1 < N_CLASS) ? sc[c1] : -FLT_MAX;
    float s2 = (c2 < N_CLASS) ? sc[c2] : -FLT_MAX;

    float m = fmaxf(s0, fmaxf(s1, s2));
#pragma unroll
    for (int o = 16; o > 0; o >>= 1) m = fmaxf(m, __shfl_xor_sync(0xffffffffu, m, o));

    float e0 = expf(s0 - m);
    float e1 = (c1 < N_CLASS) ? expf(s1 - m) : 0.0f;
    float e2 = (c2 < N_CLASS) ? expf(s2 - m) : 0.0f;
    float sum = e0 + e1 + e2;
#pragma unroll
    for (int o = 16; o > 0; o >>= 1) sum += __shfl_xor_sync(0xffffffffu, sum, o);
    float inv = 1.0f / sum;

    g_probT[c0 * R_ROIS + warp] = e0 * inv;
    if (c1 < N_CLASS) g_probT[c1 * R_ROIS + warp] = e1 * inv;
    if (c2 < N_CLASS) g_probT[c2 * R_ROIS + warp] = e2 * inv;
}

// ---------------------------------------------------------------------------
// Kernel B: one CTA per foreground class.
// ---------------------------------------------------------------------------
__global__ __launch_bounds__(256) void nms_kernel(const float* __restrict__ roi,
                                                  const float* __restrict__ roi_loc,
                                                  float* __restrict__ out,
                                                  float* __restrict__ labels) {
    const int c = blockIdx.x + 1;     // class 1..80
    const int tid = threadIdx.x;
    const int lane = tid & 31;
    const int warp = tid >> 5;
    const int NT = 256;

    __shared__ float skey[CAP];
    __shared__ int   sidx[CAP];
    __shared__ int   s_cnt;
    // fast path: decoded boxes at COMPACTION position
    __shared__ float dy0[FAST], dx0[FAST], dy1[FAST], dx1[FAST], dar[FAST];
    // fast path: SORTED arrays
    __shared__ float ssy0[FAST], ssx0[FAST], ssy1[FAST], ssx1[FAST], ssar[FAST], ssk[FAST];
    // legacy path
    __shared__ float sb[CAP * 4];
    __shared__ float sarea[CAP];
    __shared__ unsigned char skeep[CAP];

    if (tid == 0) s_cnt = 0;
    __syncthreads();

    // --- compaction + immediate decode (order arbitrary; sort is total order)
    const float* probc = g_probT + c * R_ROIS;
#pragma unroll 1
    for (int r = tid; r < R_ROIS; r += NT) {
        float p = probc[r];
        if (p > SCORE_THRESH) {
            int pos = atomicAdd(&s_cnt, 1);
            skey[pos] = p;
            sidx[pos] = r;
            if (pos < FAST) {
                float ry0 = roi[r * 4 + 0], rx0 = roi[r * 4 + 1];
                float ry1 = roi[r * 4 + 2], rx1 = roi[r * 4 + 3];
                float h = ry1 - ry0, w = rx1 - rx0;
                float cy = ry0 + 0.5f * h, cx = rx0 + 0.5f * w;
                const float* lc = roi_loc + r * (N_CLASS * 4) + c * 4;
                float dyv = lc[0] * 0.1f, dxv = lc[1] * 0.1f;
                float dhv = lc[2] * 0.2f, dwv = lc[3] * 0.2f;
                float ny = dyv * h + cy, nx = dxv * w + cx;
                float nh = expf(dhv) * h, nw = expf(dwv) * w;
                float by0 = fminf(fmaxf(ny - 0.5f * nh, 0.0f), IMG_H);
                float bx0 = fminf(fmaxf(nx - 0.5f * nw, 0.0f), IMG_W);
                float by1 = fminf(fmaxf(ny + 0.5f * nh, 0.0f), IMG_H);
                float bx1 = fminf(fmaxf(nx + 0.5f * nw, 0.0f), IMG_W);
                dy0[pos] = by0; dx0[pos] = bx0;
                dy1[pos] = by1; dx1[pos] = bx1;
                dar[pos] = (by1 - by0) * (bx1 - bx0);
            }
        }
    }
    __syncthreads();
    const int nv = s_cnt;

    if (nv <= FAST) {
        float* oc = out + (size_t)(c - 1) * R_ROIS * 5;
        float* lb = labels ? labels + (size_t)(c - 1) * R_ROIS : nullptr;

        if (warp > 0) {
            // warps 1-7: zero static tail rows [FAST, R) — flat coalesced range
            int base = tid - 32;  // 0..223
#pragma unroll 1
            for (int idx = FAST * 5 + base; idx < R_ROIS * 5; idx += (NT - 32))
                oc[idx] = 0.0f;
            if (lb) {
#pragma unroll 1
                for (int r = FAST + base; r < R_ROIS; r += (NT - 32))
                    lb[r] = -1.0f;
            }
            return;
        }

        // ---- warp 0: rank sort -> ballot NMS -> head rows [0, FAST) -----
        const unsigned FULL = 0xffffffffu;

        // 1) rank sort via shared reads (no barriers, throughput-bound)
        float kreg[4]; int ireg[4]; int rk[4];
#pragma unroll
        for (int s = 0; s < 4; s++) {
            int t = s * 32 + lane;
            kreg[s] = (t < nv) ? skey[t] : -FLT_MAX;
            ireg[s] = (t < nv) ? sidx[t] : 0x7fffffff;
            rk[s] = 0;
        }
#pragma unroll 1
        for (int m = 0; m < nv; m++) {
            float km = skey[m];
            int   im = sidx[m];
#pragma unroll
            for (int s = 0; s < 4; s++)
                rk[s] += ((km > kreg[s]) || (km == kreg[s] && im < ireg[s])) ? 1 : 0;
        }
        // scatter compaction-pos data into sorted arrays
#pragma unroll
        for (int s = 0; s < 4; s++) {
            int t = s * 32 + lane;
            if (t < nv) {
                int p = rk[s];
                ssy0[p] = dy0[t]; ssx0[p] = dx0[t];
                ssy1[p] = dy1[t]; ssx1[p] = dx1[t];
                ssar[p] = dar[t]; ssk[p]  = kreg[s];
            }
        }
        __syncwarp();

        // 2) gather sorted into registers (lane holds j = s*32+lane)
        float jy0[4], jx0[4], jy1[4], jx1[4], jar[4];
#pragma unroll
        for (int s = 0; s < 4; s++) {
            int t = s * 32 + lane;
            if (t < nv) {
                jy0[s] = ssy0[t]; jx0[s] = ssx0[t];
                jy1[s] = ssy1[t]; jx1[s] = ssx1[t];
                jar[s] = ssar[t];
            } else {
                jy0[s] = jx0[s] = jy1[s] = jx1[s] = jar[s] = 0.0f;
            }
        }

        // 3) greedy NMS; dead mask replicated in every lane (128 bits)
        unsigned long long d0 = 0ull, d1 = 0ull;
#pragma unroll 1
        for (int i = 0; i < nv; i++) {
            float iy0 = ssy0[i], ix0 = ssx0[i];
            float iy1 = ssy1[i], ix1 = ssx1[i];
            float iar = ssar[i];
            bool idead = (i < 64) ? ((d0 >> i) & 1ull) : ((d1 >> (i - 64)) & 1ull);

            bool sup[4];
#pragma unroll
            for (int s = 0; s < 4; s++) {
                int j = s * 32 + lane;
                bool jdead = (s < 2) ? ((d0 >> (j & 63)) & 1ull)
                                     : ((d1 >> (j & 63)) & 1ull);
                // IoU math independent of the dead chain (same forms as R2)
                float ty = fmaxf(iy0, jy0[s]);
                float tx = fmaxf(ix0, jx0[s]);
                float by = fminf(iy1, jy1[s]);
                float bx = fminf(ix1, jx1[s]);
                float inter = fmaxf(by - ty, 0.0f) * fmaxf(bx - tx, 0.0f);
                float iou = inter / (iar + jar[s] - inter + 1e-9f);
                sup[s] = (!idead) && (!jdead) && (j > i) && (j < nv) && (iou > NMS_THRESH);
            }
            unsigned b0 = __ballot_sync(FULL, sup[0]);
            unsigned b1 = __ballot_sync(FULL, sup[1]);
            unsigned b2 = __ballot_sync(FULL, sup[2]);
            unsigned b3 = __ballot_sync(FULL, sup[3]);
            d0 |= (unsigned long long)b0 | ((unsigned long long)b1 << 32);
            d1 |= (unsigned long long)b2 | ((unsigned long long)b3 << 32);
        }

        // 4) head output rows [0, FAST): kept-or-zero from sorted shared
#pragma unroll 1
        for (int idx = lane; idx < FAST * 5; idx += 32) {
            int r = idx / 5, f = idx - r * 5;
            bool kp = (r < nv) &&
                      !((r < 64) ? ((d0 >> r) & 1ull) : ((d1 >> (r - 64)) & 1ull));
            float v;
            if      (f == 0) v = ssy0[r];
            else if (f == 1) v = ssx0[r];
            else if (f == 2) v = ssy1[r];
            else if (f == 3) v = ssx1[r];
            else             v = ssk[r];
            oc[idx] = kp ? v : 0.0f;
        }
        if (lb) {
#pragma unroll
            for (int s = 0; s < 4; s++) {
                int r = s * 32 + lane;
                bool kp = (r < nv) &&
                          !((r < 64) ? ((d0 >> r) & 1ull) : ((d1 >> (r - 64)) & 1ull));
                lb[r] = kp ? (float)(c - 1) : -1.0f;
            }
        }
        return;
    }

    // ---------------- legacy path (nv > FAST; uniform branch) -------------
    int P = 1;
    while (P < nv) P <<= 1;
    for (int i = nv + tid; i < P; i += NT) { skey[i] = -FLT_MAX; sidx[i] = 0x7fffffff; }
    __syncthreads();
    for (int k = 2; k <= P; k <<= 1) {
        for (int j = k >> 1; j > 0; j >>= 1) {
            for (int i = tid; i < P; i += NT) {
                int ixj = i ^ j;
                if (ixj > i) {
                    float a = skey[i],  b = skey[ixj];
                    int   ia = sidx[i], ib = sidx[ixj];
                    bool desc = ((i & k) == 0);
                    bool before_ba = (b > a) || (b == a && ib < ia);
                    bool before_ab = (a > b) || (a == b && ia < ib);
                    if (desc ? before_ba : before_ab) {
                        skey[i] = b;  skey[ixj] = a;
                        sidx[i] = ib; sidx[ixj] = ia;
                    }
                }
            }
            __syncthreads();
        }
    }

#pragma unroll 1
    for (int kk = tid; kk < nv; kk += NT) {
        int r = sidx[kk];
        float y0 = roi[r * 4 + 0], x0 = roi[r * 4 + 1];
        float y1 = roi[r * 4 + 2], x1 = roi[r * 4 + 3];
        float h = y1 - y0, w = x1 - x0;
        float cy = y0 + 0.5f * h, cx = x0 + 0.5f * w;
        const float* lc = roi_loc + r * (N_CLASS * 4) + c * 4;
        float dyv = lc[0] * 0.1f, dxv = lc[1] * 0.1f;
        float dhv = lc[2] * 0.2f, dwv = lc[3] * 0.2f;
        float ny = dyv * h + cy, nx = dxv * w + cx;
        float nh = expf(dhv) * h, nw = expf(dwv) * w;
        float by0 = fminf(fmaxf(ny - 0.5f * nh, 0.0f), IMG_H);
        float bx0 = fminf(fmaxf(nx - 0.5f * nw, 0.0f), IMG_W);
        float by1 = fminf(fmaxf(ny + 0.5f * nh, 0.0f), IMG_H);
        float bx1 = fminf(fmaxf(nx + 0.5f * nw, 0.0f), IMG_W);
        sb[kk * 4 + 0] = by0; sb[kk * 4 + 1] = bx0;
        sb[kk * 4 + 2] = by1; sb[kk * 4 + 3] = bx1;
        sarea[kk] = (by1 - by0) * (bx1 - bx0);
        skeep[kk] = 1;
    }
    __syncthreads();

    if (tid < 32) {
#pragma unroll 1
        for (int i = 0; i < nv; i++) {
            if (skeep[i]) {
                float iy0 = sb[i * 4 + 0], ix0 = sb[i * 4 + 1];
                float iy1 = sb[i * 4 + 2], ix1 = sb[i * 4 + 3];
                float iar = sarea[i];
#pragma unroll 1
                for (int jj = i + 1 + tid; jj < nv; jj += 32) {
                    if (skeep[jj]) {
                        float ty = fmaxf(iy0, sb[jj * 4 + 0]);
                        float tx = fmaxf(ix0, sb[jj * 4 + 1]);
                        float by = fminf(iy1, sb[jj * 4 + 2]);
                        float bx = fminf(ix1, sb[jj * 4 + 3]);
                        float inter = fmaxf(by - ty, 0.0f) * fmaxf(bx - tx, 0.0f);
                        float iou = inter / (iar + sarea[jj] - inter + 1e-9f);
                        if (iou > NMS_THRESH) skeep[jj] = 0;
                    }
                }
            }
            __syncwarp();
        }
    }
    __syncthreads();

    float* oc = out + (size_t)(c - 1) * R_ROIS * 5;
#pragma unroll 1
    for (int r = tid; r < R_ROIS; r += NT) {
        bool kp = (r < nv) && skeep[r];
        oc[r * 5 + 0] = kp ? sb[r * 4 + 0] : 0.0f;
        oc[r * 5 + 1] = kp ? sb[r * 4 + 1] : 0.0f;
        oc[r * 5 + 2] = kp ? sb[r * 4 + 2] : 0.0f;
        oc[r * 5 + 3] = kp ? sb[r * 4 + 3] : 0.0f;
        oc[r * 5 + 4] = kp ? skey[r]       : 0.0f;
        if (labels)
            labels[(size_t)(c - 1) * R_ROIS + r] = kp ? (float)(c - 1) : -1.0f;
    }
}

extern "C" void kernel_launch(void* const* d_in, const int* in_sizes, int n_in,
                              void* d_out, int out_size) {
    const float* roi       = (const float*)d_in[0];  // [1000,4]
    const float* roi_loc   = (const float*)d_in[1];  // [1000,324]
    const float* roi_score = (const float*)d_in[2];  // [1000,81]

    float* out = (float*)d_out;
    const int out_elems   = N_FG * R_ROIS * 5;  // 400000
    const int label_elems = N_FG * R_ROIS;      // 80000
    float* labels = (out_size >= out_elems + label_elems) ? (out + out_elems)
                                                          : nullptr;

    softmax_kernel<<<(R_ROIS * 32 + 255) / 256, 256>>>(roi_score);
    nms_kernel<<<N_FG, 256>>>(roi, roi_loc, out, labels);
}

// round 5
// speedup vs baseline: 1.6032x; 1.6032x over previous
#include <cuda_runtime.h>
#include <cuda_bf16.h>
#include <float.h>
#include <math.h>

#define R_ROIS 1000
#define N_CLASS 81
#define N_FG 80
#define IMG_H 600.0f
#define IMG_W 800.0f
#define SCORE_THRESH 0.05f
#define NMS_THRESH 0.5f
#define CAP 1024      // per-class candidate capacity (pow2 for bitonic)
#define CSTRIDE 32    // 128B padding between per-class counters

// Scratch (no cudaMalloc). g_cnt is zero-initialized at module load and
// reset to zero by kernel B every launch -> deterministic across replays.
__device__ int   g_cnt[N_FG * CSTRIDE];
__device__ float g_cp[N_FG * CAP];
__device__ int   g_cr[N_FG * CAP];

// ---------------------------------------------------------------------------
// Kernel A: softmax over classes (one WARP per RoI) + direct candidate
// emission for probs > SCORE_THRESH. No dense prob array.
// ---------------------------------------------------------------------------
__global__ __launch_bounds__(256) void softmax_kernel(const float* __restrict__ roi_score) {
    const int warp = (blockIdx.x * blockDim.x + threadIdx.x) >> 5;
    const int lane = threadIdx.x & 31;
    if (warp >= R_ROIS) return;

    const float* sc = roi_score + warp * N_CLASS;
    int c0 = lane, c1 = lane + 32, c2 = lane + 64;
    float s0 = sc[c0];
    float s1 = (c1 < N_CLASS) ? sc[c1] : -FLT_MAX;
    float s2 = (c2 < N_CLASS) ? sc[c2] : -FLT_MAX;

    float m = fmaxf(s0, fmaxf(s1, s2));
#pragma unroll
    for (int o = 16; o > 0; o >>= 1) m = fmaxf(m, __shfl_xor_sync(0xffffffffu, m, o));

    float e0 = expf(s0 - m);
    float e1 = (c1 < N_CLASS) ? expf(s1 - m) : 0.0f;
    float e2 = (c2 < N_CLASS) ? expf(s2 - m) : 0.0f;
    float sum = e0 + e1 + e2;
#pragma unroll
    for (int o = 16; o > 0; o >>= 1) sum += __shfl_xor_sync(0xffffffffu, sum, o);
    float inv = 1.0f / sum;

    float p0 = e0 * inv, p1 = e1 * inv, p2 = e2 * inv;
    // emit candidates (skip background class 0)
    if (c0 >= 1 && p0 > SCORE_THRESH) {
        int fg = c0 - 1;
        int pos = atomicAdd(&g_cnt[fg * CSTRIDE], 1);
        if (pos < CAP) { g_cp[fg * CAP + pos] = p0; g_cr[fg * CAP + pos] = warp; }
    }
    if (p1 > SCORE_THRESH) {                      // c1 in [32,64): always fg
        int fg = c1 - 1;
        int pos = atomicAdd(&g_cnt[fg * CSTRIDE], 1);
        if (pos < CAP) { g_cp[fg * CAP + pos] = p1; g_cr[fg * CAP + pos] = warp; }
    }
    if (c2 < N_CLASS && p2 > SCORE_THRESH) {
        int fg = c2 - 1;
        int pos = atomicAdd(&g_cnt[fg * CSTRIDE], 1);
        if (pos < CAP) { g_cp[fg * CAP + pos] = p2; g_cr[fg * CAP + pos] = warp; }
    }
}

// ---------------------------------------------------------------------------
// Kernel B: one CTA per foreground class. Body identical to the proven R2
// kernel except the compaction scan is replaced by a candidate-list load.
// ---------------------------------------------------------------------------
__global__ __launch_bounds__(256) void nms_kernel(const float* __restrict__ roi,
                                                  const float* __restrict__ roi_loc,
                                                  float* __restrict__ out,
                                                  float* __restrict__ labels) {
    const int fg = blockIdx.x;        // 0..79
    const int c = fg + 1;             // class 1..80
    const int tid = threadIdx.x;
    const int NT = 256;

    __shared__ float skey[CAP];
    __shared__ int   sidx[CAP];
    __shared__ float sb[CAP * 4];
    __shared__ float sarea[CAP];
    __shared__ unsigned char skeep[CAP];

    // 1) load candidate list (order arbitrary: sort is a strict total order)
    int nv = g_cnt[fg * CSTRIDE];
    if (nv > CAP) nv = CAP;
#pragma unroll 1
    for (int t = tid; t < nv; t += NT) {
        skey[t] = g_cp[fg * CAP + t];
        sidx[t] = g_cr[fg * CAP + t];
    }
    __syncthreads();
    if (tid == 0) g_cnt[fg * CSTRIDE] = 0;   // reset for next launch

    // 2) bitonic sort over next-pow2 >= nv (desc by score, asc idx on ties)
    int P = 1;
    while (P < nv) P <<= 1;
    for (int i = nv + tid; i < P; i += NT) { skey[i] = -FLT_MAX; sidx[i] = 0x7fffffff; }
    __syncthreads();
    for (int k = 2; k <= P; k <<= 1) {
        for (int j = k >> 1; j > 0; j >>= 1) {
            for (int i = tid; i < P; i += NT) {
                int ixj = i ^ j;
                if (ixj > i) {
                    float a = skey[i],  b = skey[ixj];
                    int   ia = sidx[i], ib = sidx[ixj];
                    bool desc = ((i & k) == 0);
                    bool before_ba = (b > a) || (b == a && ib < ia);
                    bool before_ab = (a > b) || (a == b && ia < ib);
                    if (desc ? before_ba : before_ab) {
                        skey[i] = b;  skey[ixj] = a;
                        sidx[i] = ib; sidx[ixj] = ia;
                    }
                }
            }
            __syncthreads();
        }
    }

    // 3) decode boxes ONLY for the nv survivors (parallel, 256 threads)
#pragma unroll 1
    for (int kk = tid; kk < nv; kk += NT) {
        int r = sidx[kk];
        float y0 = roi[r * 4 + 0];
        float x0 = roi[r * 4 + 1];
        float y1 = roi[r * 4 + 2];
        float x1 = roi[r * 4 + 3];
        float h = y1 - y0, w = x1 - x0;
        float cy = y0 + 0.5f * h, cx = x0 + 0.5f * w;
        const float* lc = roi_loc + r * (N_CLASS * 4) + c * 4;
        float dy = lc[0] * 0.1f;
        float dx = lc[1] * 0.1f;
        float dh = lc[2] * 0.2f;
        float dw = lc[3] * 0.2f;
        float ny = dy * h + cy;
        float nx = dx * w + cx;
        float nh = expf(dh) * h;
        float nw = expf(dw) * w;
        float by0 = fminf(fmaxf(ny - 0.5f * nh, 0.0f), IMG_H);
        float bx0 = fminf(fmaxf(nx - 0.5f * nw, 0.0f), IMG_W);
        float by1 = fminf(fmaxf(ny + 0.5f * nh, 0.0f), IMG_H);
        float bx1 = fminf(fmaxf(nx + 0.5f * nw, 0.0f), IMG_W);
        sb[kk * 4 + 0] = by0;
        sb[kk * 4 + 1] = bx0;
        sb[kk * 4 + 2] = by1;
        sb[kk * 4 + 3] = bx1;
        sarea[kk] = (by1 - by0) * (bx1 - bx0);
        skeep[kk] = 1;
    }
    __syncthreads();

    // 4) greedy NMS, single warp (no block barriers). Exact match to the
    //    reference fori_loop restricted to the valid prefix.
    if (tid < 32) {
#pragma unroll 1
        for (int i = 0; i < nv; i++) {
            if (skeep[i]) {
                float iy0 = sb[i * 4 + 0], ix0 = sb[i * 4 + 1];
                float iy1 = sb[i * 4 + 2], ix1 = sb[i * 4 + 3];
                float iar = sarea[i];
#pragma unroll 1
                for (int jj = i + 1 + tid; jj < nv; jj += 32) {
                    if (skeep[jj]) {
                        float ty = fmaxf(iy0, sb[jj * 4 + 0]);
                        float tx = fmaxf(ix0, sb[jj * 4 + 1]);
                        float by = fminf(iy1, sb[jj * 4 + 2]);
                        float bx = fminf(ix1, sb[jj * 4 + 3]);
                        float wh0 = fmaxf(by - ty, 0.0f);
                        float wh1 = fmaxf(bx - tx, 0.0f);
                        float inter = wh0 * wh1;
                        float iou = inter / (iar + sarea[jj] - inter + 1e-9f);
                        if (iou > NMS_THRESH) skeep[jj] = 0;
                    }
                }
            }
            __syncwarp();
        }
    }
    __syncthreads();

    // 5) dense output: rows [0,nv) kept-or-zero, rows [nv,1000) zero / -1
    float* oc = out + (size_t)fg * R_ROIS * 5;
#pragma unroll 1
    for (int r = tid; r < R_ROIS; r += NT) {
        bool kp = (r < nv) && skeep[r];
        oc[r * 5 + 0] = kp ? sb[r * 4 + 0] : 0.0f;
        oc[r * 5 + 1] = kp ? sb[r * 4 + 1] : 0.0f;
        oc[r * 5 + 2] = kp ? sb[r * 4 + 2] : 0.0f;
        oc[r * 5 + 3] = kp ? sb[r * 4 + 3] : 0.0f;
        oc[r * 5 + 4] = kp ? skey[r]       : 0.0f;
        if (labels)
            labels[(size_t)fg * R_ROIS + r] = kp ? (float)fg : -1.0f;
    }
}

extern "C" void kernel_launch(void* const* d_in, const int* in_sizes, int n_in,
                              void* d_out, int out_size) {
    const float* roi       = (const float*)d_in[0];  // [1000,4]
    const float* roi_loc   = (const float*)d_in[1];  // [1000,324]
    const float* roi_score = (const float*)d_in[2];  // [1000,81]

    float* out = (float*)d_out;
    const int out_elems   = N_FG * R_ROIS * 5;  // 400000
    const int label_elems = N_FG * R_ROIS;      // 80000
    float* labels = (out_size >= out_elems + label_elems) ? (out + out_elems)
                                                          : nullptr;

    softmax_kernel<<<(R_ROIS * 32 + 255) / 256, 256>>>(roi_score);
    nms_kernel<<<N_FG, 256>>>(roi, roi_loc, out, labels);
}

// round 6
// speedup vs baseline: 2.6607x; 1.6596x over previous
#include <cuda_runtime.h>
#include <cuda_bf16.h>
#include <float.h>
#include <math.h>

#define R_ROIS 1000
#define N_CLASS 81
#define N_FG 80
#define IMG_H 600.0f
#define IMG_W 800.0f
#define SCORE_THRESH 0.05f
#define NMS_THRESH 0.5f
#define CAP 1024      // per-class candidate capacity (pow2 for legacy bitonic)
#define FAST 128      // matrix-NMS fast-path capacity
#define CSTRIDE 32    // 128B padding between per-class counters

// Scratch (no cudaMalloc). g_cnt zero-initialized at module load and reset
// by kernel B each launch -> deterministic across graph replays.
__device__ int   g_cnt[N_FG * CSTRIDE];
__device__ float g_cp[N_FG * CAP];
__device__ int   g_cr[N_FG * CAP];

// ---------------------------------------------------------------------------
// Kernel A: softmax (one WARP per RoI) + candidate emission. (R5, unchanged)
// ---------------------------------------------------------------------------
__global__ __launch_bounds__(256) void softmax_kernel(const float* __restrict__ roi_score) {
    const int warp = (blockIdx.x * blockDim.x + threadIdx.x) >> 5;
    const int lane = threadIdx.x & 31;
    if (warp >= R_ROIS) return;

    const float* sc = roi_score + warp * N_CLASS;
    int c0 = lane, c1 = lane + 32, c2 = lane + 64;
    float s0 = sc[c0];
    float s1 = (c1 < N_CLASS) ? sc[c1] : -FLT_MAX;
    float s2 = (c2 < N_CLASS) ? sc[c2] : -FLT_MAX;

    float m = fmaxf(s0, fmaxf(s1, s2));
#pragma unroll
    for (int o = 16; o > 0; o >>= 1) m = fmaxf(m, __shfl_xor_sync(0xffffffffu, m, o));

    float e0 = expf(s0 - m);
    float e1 = (c1 < N_CLASS) ? expf(s1 - m) : 0.0f;
    float e2 = (c2 < N_CLASS) ? expf(s2 - m) : 0.0f;
    float sum = e0 + e1 + e2;
#pragma unroll
    for (int o = 16; o > 0; o >>= 1) sum += __shfl_xor_sync(0xffffffffu, sum, o);
    float inv = 1.0f / sum;

    float p0 = e0 * inv, p1 = e1 * inv, p2 = e2 * inv;
    if (c0 >= 1 && p0 > SCORE_THRESH) {
        int fg = c0 - 1;
        int pos = atomicAdd(&g_cnt[fg * CSTRIDE], 1);
        if (pos < CAP) { g_cp[fg * CAP + pos] = p0; g_cr[fg * CAP + pos] = warp; }
    }
    if (p1 > SCORE_THRESH) {
        int fg = c1 - 1;
        int pos = atomicAdd(&g_cnt[fg * CSTRIDE], 1);
        if (pos < CAP) { g_cp[fg * CAP + pos] = p1; g_cr[fg * CAP + pos] = warp; }
    }
    if (c2 < N_CLASS && p2 > SCORE_THRESH) {
        int fg = c2 - 1;
        int pos = atomicAdd(&g_cnt[fg * CSTRIDE], 1);
        if (pos < CAP) { g_cp[fg * CAP + pos] = p2; g_cr[fg * CAP + pos] = warp; }
    }
}

// ---------------------------------------------------------------------------
// Kernel B: one CTA per foreground class. Matrix-NMS fast path (nv <= 128):
// parallel rank sort, parallel suppression matrix, ~1k-cycle serial scan.
// ---------------------------------------------------------------------------
__global__ __launch_bounds__(256) void nms_kernel(const float* __restrict__ roi,
                                                  const float* __restrict__ roi_loc,
                                                  float* __restrict__ out,
                                                  float* __restrict__ labels) {
    const int fg = blockIdx.x;        // 0..79
    const int c = fg + 1;             // class 1..80
    const int tid = threadIdx.x;
    const int NT = 256;

    __shared__ float skey[CAP];
    __shared__ int   sidx[CAP];
    // fast path
    __shared__ float sy0[FAST], sx0[FAST], sy1[FAST], sx1[FAST], sar[FAST];
    __shared__ unsigned long long sm0[FAST], sm1[FAST];
    __shared__ unsigned long long sd0, sd1;
    // legacy path
    __shared__ float sb[CAP * 4];
    __shared__ float sarea[CAP];
    __shared__ unsigned char skeep[CAP];

    // 1) load candidate list (order arbitrary; sort is a strict total order)
    int nv = g_cnt[fg * CSTRIDE];
    if (nv > CAP) nv = CAP;
#pragma unroll 1
    for (int t = tid; t < nv; t += NT) {
        skey[t] = g_cp[fg * CAP + t];
        sidx[t] = g_cr[fg * CAP + t];
    }
    __syncthreads();
    if (tid == 0) g_cnt[fg * CSTRIDE] = 0;   // reset for next launch

    if (nv <= FAST) {
        // ---- 2) parallel rank sort (one element per thread) --------------
        float myk = 0.0f; int myr = 0; int rank = 0;
        if (tid < nv) {
            myk = skey[tid]; myr = sidx[tid];
#pragma unroll 1
            for (int m = 0; m < nv; m++) {
                float km = skey[m];      // broadcast LDS (lockstep m)
                int   im = sidx[m];
                rank += ((km > myk) || (km == myk && im < myr)) ? 1 : 0;
            }
        }
        __syncthreads();
        if (tid < nv) { skey[rank] = myk; sidx[rank] = myr; }
        __syncthreads();

        // ---- 3) decode at sorted position (thread t owns element t) ------
        float by0 = 0.f, bx0 = 0.f, by1 = 0.f, bx1 = 0.f, bar = 0.f;
        if (tid < nv) {
            int r = sidx[tid];
            float ry0 = roi[r * 4 + 0], rx0 = roi[r * 4 + 1];
            float ry1 = roi[r * 4 + 2], rx1 = roi[r * 4 + 3];
            float h = ry1 - ry0, w = rx1 - rx0;
            float cy = ry0 + 0.5f * h, cx = rx0 + 0.5f * w;
            const float* lc = roi_loc + r * (N_CLASS * 4) + c * 4;
            float dy = lc[0] * 0.1f, dx = lc[1] * 0.1f;
            float dh = lc[2] * 0.2f, dw = lc[3] * 0.2f;
            float ny = dy * h + cy, nx = dx * w + cx;
            float nh = expf(dh) * h, nw = expf(dw) * w;
            by0 = fminf(fmaxf(ny - 0.5f * nh, 0.0f), IMG_H);
            bx0 = fminf(fmaxf(nx - 0.5f * nw, 0.0f), IMG_W);
            by1 = fminf(fmaxf(ny + 0.5f * nh, 0.0f), IMG_H);
            bx1 = fminf(fmaxf(nx + 0.5f * nw, 0.0f), IMG_W);
            bar = (by1 - by0) * (bx1 - bx0);
            sy0[tid] = by0; sx0[tid] = bx0;
            sy1[tid] = by1; sx1[tid] = bx1;
            sar[tid] = bar;
        }
        __syncthreads();

        // ---- 4) suppression matrix: thread i -> 128-bit mask of j>i ------
        if (tid < nv) {
            unsigned long long m0 = 0ull, m1 = 0ull;
#pragma unroll 1
            for (int j = tid + 1; j < nv; j++) {
                float ty = fmaxf(by0, sy0[j]);
                float tx = fmaxf(bx0, sx0[j]);
                float by = fminf(by1, sy1[j]);
                float bx = fminf(bx1, sx1[j]);
                float inter = fmaxf(by - ty, 0.0f) * fmaxf(bx - tx, 0.0f);
                float iou = inter / (bar + sar[j] - inter + 1e-9f);
                if (iou > NMS_THRESH) {
                    if (j < 64) m0 |= 1ull << j;
                    else        m1 |= 1ull << (j - 64);
                }
            }
            sm0[tid] = m0; sm1[tid] = m1;
        }
        __syncthreads();

        // ---- 5) serial greedy scan: pure ALU chain, loads off-chain ------
        if (tid == 0) {
            unsigned long long d0 = 0ull, d1 = 0ull;
#pragma unroll 4
            for (int i = 0; i < nv; i++) {
                unsigned long long m0 = sm0[i];   // address dep on i only
                unsigned long long m1 = sm1[i];
                unsigned long long bit = (i < 64) ? (d0 >> i) : (d1 >> (i - 64));
                if (!(bit & 1ull)) { d0 |= m0; d1 |= m1; }
            }
            sd0 = d0; sd1 = d1;
        }
        __syncthreads();

        // ---- 6) epilogue: all 1000 rows --------------------------------
        unsigned long long d0 = sd0, d1 = sd1;
        float* oc = out + (size_t)fg * R_ROIS * 5;
#pragma unroll 1
        for (int r = tid; r < R_ROIS; r += NT) {
            bool kp = false;
            if (r < nv) {
                unsigned long long bit = (r < 64) ? (d0 >> r) : (d1 >> (r - 64));
                kp = !(bit & 1ull);
            }
            oc[r * 5 + 0] = kp ? sy0[r] : 0.0f;
            oc[r * 5 + 1] = kp ? sx0[r] : 0.0f;
            oc[r * 5 + 2] = kp ? sy1[r] : 0.0f;
            oc[r * 5 + 3] = kp ? sx1[r] : 0.0f;
            oc[r * 5 + 4] = kp ? skey[r] : 0.0f;
            if (labels)
                labels[(size_t)fg * R_ROIS + r] = kp ? (float)fg : -1.0f;
        }
        return;
    }

    // ---------------- legacy path (nv > FAST; uniform branch) -------------
    int P = 1;
    while (P < nv) P <<= 1;
    for (int i = nv + tid; i < P; i += NT) { skey[i] = -FLT_MAX; sidx[i] = 0x7fffffff; }
    __syncthreads();
    for (int k = 2; k <= P; k <<= 1) {
        for (int j = k >> 1; j > 0; j >>= 1) {
            for (int i = tid; i < P; i += NT) {
                int ixj = i ^ j;
                if (ixj > i) {
                    float a = skey[i],  b = skey[ixj];
                    int   ia = sidx[i], ib = sidx[ixj];
                    bool desc = ((i & k) == 0);
                    bool before_ba = (b > a) || (b == a && ib < ia);
                    bool before_ab = (a > b) || (a == b && ia < ib);
                    if (desc ? before_ba : before_ab) {
                        skey[i] = b;  skey[ixj] = a;
                        sidx[i] = ib; sidx[ixj] = ia;
                    }
                }
            }
            __syncthreads();
        }
    }

#pragma unroll 1
    for (int kk = tid; kk < nv; kk += NT) {
        int r = sidx[kk];
        float y0 = roi[r * 4 + 0], x0 = roi[r * 4 + 1];
        float y1 = roi[r * 4 + 2], x1 = roi[r * 4 + 3];
        float h = y1 - y0, w = x1 - x0;
        float cy = y0 + 0.5f * h, cx = x0 + 0.5f * w;
        const float* lc = roi_loc + r * (N_CLASS * 4) + c * 4;
        float dy = lc[0] * 0.1f, dx = lc[1] * 0.1f;
        float dh = lc[2] * 0.2f, dw = lc[3] * 0.2f;
        float ny = dy * h + cy, nx = dx * w + cx;
        float nh = expf(dh) * h, nw = expf(dw) * w;
        float by0 = fminf(fmaxf(ny - 0.5f * nh, 0.0f), IMG_H);
        float bx0 = fminf(fmaxf(nx - 0.5f * nw, 0.0f), IMG_W);
        float by1 = fminf(fmaxf(ny + 0.5f * nh, 0.0f), IMG_H);
        float bx1 = fminf(fmaxf(nx + 0.5f * nw, 0.0f), IMG_W);
        sb[kk * 4 + 0] = by0; sb[kk * 4 + 1] = bx0;
        sb[kk * 4 + 2] = by1; sb[kk * 4 + 3] = bx1;
        sarea[kk] = (by1 - by0) * (bx1 - bx0);
        skeep[kk] = 1;
    }
    __syncthreads();

    if (tid < 32) {
#pragma unroll 1
        for (int i = 0; i < nv; i++) {
            if (skeep[i]) {
                float iy0 = sb[i * 4 + 0], ix0 = sb[i * 4 + 1];
                float iy1 = sb[i * 4 + 2], ix1 = sb[i * 4 + 3];
                float iar = sarea[i];
#pragma unroll 1
                for (int jj = i + 1 + tid; jj < nv; jj += 32) {
                    if (skeep[jj]) {
                        float ty = fmaxf(iy0, sb[jj * 4 + 0]);
                        float tx = fmaxf(ix0, sb[jj * 4 + 1]);
                        float by = fminf(iy1, sb[jj * 4 + 2]);
                        float bx = fminf(ix1, sb[jj * 4 + 3]);
                        float inter = fmaxf(by - ty, 0.0f) * fmaxf(bx - tx, 0.0f);
                        float iou = inter / (iar + sarea[jj] - inter + 1e-9f);
                        if (iou > NMS_THRESH) skeep[jj] = 0;
                    }
                }
            }
            __syncwarp();
        }
    }
    __syncthreads();

    float* oc = out + (size_t)fg * R_ROIS * 5;
#pragma unroll 1
    for (int r = tid; r < R_ROIS; r += NT) {
        bool kp = (r < nv) && skeep[r];
        oc[r * 5 + 0] = kp ? sb[r * 4 + 0] : 0.0f;
        oc[r * 5 + 1] = kp ? sb[r * 4 + 1] : 0.0f;
        oc[r * 5 + 2] = kp ? sb[r * 4 + 2] : 0.0f;
        oc[r * 5 + 3] = kp ? sb[r * 4 + 3] : 0.0f;
        oc[r * 5 + 4] = kp ? skey[r]       : 0.0f;
        if (labels)
            labels[(size_t)fg * R_ROIS + r] = kp ? (float)fg : -1.0f;
    }
}

extern "C" void kernel_launch(void* const* d_in, const int* in_sizes, int n_in,
                              void* d_out, int out_size) {
    const float* roi       = (const float*)d_in[0];  // [1000,4]
    const float* roi_loc   = (const float*)d_in[1];  // [1000,324]
    const float* roi_score = (const float*)d_in[2];  // [1000,81]

    float* out = (float*)d_out;
    const int out_elems   = N_FG * R_ROIS * 5;  // 400000
    const int label_elems = N_FG * R_ROIS;      // 80000
    float* labels = (out_size >= out_elems + label_elems) ? (out + out_elems)
                                                          : nullptr;

    softmax_kernel<<<(R_ROIS * 32 + 255) / 256, 256>>>(roi_score);
    nms_kernel<<<N_FG, 256>>>(roi, roi_loc, out, labels);
}